// round 7
// baseline (speedup 1.0000x reference)
#include <cuda_runtime.h>
#include <cstdint>

#define NUM_IN 25   // 2*(8+2)+4+1
#define NUM_OUT 20  // 2*8+4
#define J_PAIRS 13  // 25 layer-1 rows -> 13 f32x2 pairs (last hi lane padded 0)
#define J_STRIDE 14 // u64 per k-row in shared (16B-aligned, 112B)
#define I_PAIRS 10  // 20 layer-2 rows -> 10 pairs exactly

typedef unsigned long long u64;

// Constant bank: layer-2 weights + both biases (LDC port).
struct __align__(16) CParams {
    u64 w2[25][10];  // [k][ip] = {W2[2ip][k], W2[2ip+1][k]}
    u64 b1[14];      // j-paired, padded
    u64 b2[10];
};
__constant__ CParams cP;
__device__ CParams dScratch;

__device__ __forceinline__ u64 dpack(float lo, float hi) {
    return (u64)__float_as_uint(lo) | ((u64)__float_as_uint(hi) << 32);
}
__device__ __forceinline__ u64 pk2s(float v) {   // splat {v, v}
    u64 r;
    asm("mov.b64 %0, {%1, %1};" : "=l"(r) : "f"(v));
    return r;
}
__device__ __forceinline__ void upk2(u64 v, float& lo, float& hi) {
    asm("mov.b64 {%0, %1}, %2;" : "=f"(lo), "=f"(hi) : "l"(v));
}
__device__ __forceinline__ u64 ffma2(u64 a, u64 b, u64 c) {
    u64 d;
    asm("fma.rn.f32x2 %0, %1, %2, %3;" : "=l"(d) : "l"(a), "l"(b), "l"(c));
    return d;
}

// ---- Prep: pack layer-2 weights + biases into dScratch (-> cP) ----
__global__ void prep_kernel(const float* __restrict__ b1,
                            const float* __restrict__ W2, const float* __restrict__ b2)
{
    int t = blockIdx.x * blockDim.x + threadIdx.x;
    int stride = gridDim.x * blockDim.x;
    for (int i = t; i < 25 * 10; i += stride) {
        int k = i / 10, ip = i % 10;
        dScratch.w2[k][ip] = dpack(W2[(2 * ip) * NUM_IN + k], W2[(2 * ip + 1) * NUM_IN + k]);
    }
    for (int i = t; i < 14; i += stride) {
        float lo = 0.0f, hi = 0.0f;
        if (i < J_PAIRS) {
            lo = b1[2 * i];
            if (2 * i + 1 < NUM_IN) hi = b1[2 * i + 1];
        }
        dScratch.b1[i] = dpack(lo, hi);
    }
    for (int i = t; i < 10; i += stride)
        dScratch.b2[i] = dpack(b2[2 * i], b2[2 * i + 1]);
}

// ---- Main: 2 edges/thread. W1 via shared (LDS port), W2 via const (LDC port). ----
__global__ void __launch_bounds__(128, 4)
edge_mlp_kernel(const float* __restrict__ r,
                const float* __restrict__ a_data,
                const float* __restrict__ a_material,
                const float* __restrict__ a_influx,
                const float* __restrict__ b_data,
                const float* __restrict__ b_material,
                const float* __restrict__ b_influx,
                const float* __restrict__ e_data,
                const float* __restrict__ W1g,
                float* __restrict__ out,
                int E)
{
    // Shared: W1 transposed & j-paired, rows of 14 u64 (16B aligned).
    __shared__ __align__(16) u64 sW1[25 * J_STRIDE];

    for (int i = threadIdx.x; i < 25 * J_STRIDE; i += blockDim.x) {
        int k = i / J_STRIDE, jp = i % J_STRIDE;
        float lo = 0.0f, hi = 0.0f;
        if (jp < J_PAIRS) {
            lo = W1g[(2 * jp) * NUM_IN + k];
            if (2 * jp + 1 < NUM_IN) hi = W1g[(2 * jp + 1) * NUM_IN + k];
        }
        sW1[i] = dpack(lo, hi);
    }

    long pair = (long)blockIdx.x * blockDim.x + threadIdx.x;
    long e0 = pair * 2;
    bool active = (e0 < E);
    long ee0 = active ? e0 : 0;
    bool have_e1 = (e0 + 1 < E);
    long ee1 = have_e1 ? (e0 + 1) : ee0;

    // ---- Gather inputs for both edges (overlaps with smem fill) ----
    const float4* ad4 = reinterpret_cast<const float4*>(a_data);
    const float4* bd4 = reinterpret_cast<const float4*>(b_data);
    const float4* ed4 = reinterpret_cast<const float4*>(e_data);

    float x0[NUM_IN], x1[NUM_IN];
    x0[0] = r[ee0]; x1[0] = r[ee1];
    {
        float4 p = ad4[2 * ee0], q = ad4[2 * ee1];
        x0[1] = p.x; x0[2] = p.y; x0[3] = p.z; x0[4] = p.w;
        x1[1] = q.x; x1[2] = q.y; x1[3] = q.z; x1[4] = q.w;
        p = ad4[2 * ee0 + 1]; q = ad4[2 * ee1 + 1];
        x0[5] = p.x; x0[6] = p.y; x0[7] = p.z; x0[8] = p.w;
        x1[5] = q.x; x1[6] = q.y; x1[7] = q.z; x1[8] = q.w;
    }
    x0[9]  = a_material[ee0]; x1[9]  = a_material[ee1];
    x0[10] = a_influx[ee0];   x1[10] = a_influx[ee1];
    {
        float4 p = bd4[2 * ee0], q = bd4[2 * ee1];
        x0[11] = p.x; x0[12] = p.y; x0[13] = p.z; x0[14] = p.w;
        x1[11] = q.x; x1[12] = q.y; x1[13] = q.z; x1[14] = q.w;
        p = bd4[2 * ee0 + 1]; q = bd4[2 * ee1 + 1];
        x0[15] = p.x; x0[16] = p.y; x0[17] = p.z; x0[18] = p.w;
        x1[15] = q.x; x1[16] = q.y; x1[17] = q.z; x1[18] = q.w;
    }
    x0[19] = b_material[ee0]; x1[19] = b_material[ee1];
    x0[20] = b_influx[ee0];   x1[20] = b_influx[ee1];
    {
        float4 p = ed4[ee0], q = ed4[ee1];
        x0[21] = p.x; x0[22] = p.y; x0[23] = p.z; x0[24] = p.w;
        x1[21] = q.x; x1[22] = q.y; x1[23] = q.z; x1[24] = q.w;
    }

    __syncthreads();

    // ---- Layer 1: weights via LDS.128 broadcast (shared port) ----
    u64 acc0[J_PAIRS], acc1[J_PAIRS];
    #pragma unroll
    for (int p = 0; p < J_PAIRS; p++) { acc0[p] = cP.b1[p]; acc1[p] = cP.b1[p]; }

    #pragma unroll
    for (int k = 0; k < NUM_IN; k++) {
        u64 xk0 = pk2s(x0[k]);
        u64 xk1 = pk2s(x1[k]);
        const ulonglong2* wv = reinterpret_cast<const ulonglong2*>(sW1 + k * J_STRIDE);
        #pragma unroll
        for (int q = 0; q < 6; q++) {
            ulonglong2 w = wv[q];
            acc0[2 * q]     = ffma2(w.x, xk0, acc0[2 * q]);
            acc1[2 * q]     = ffma2(w.x, xk1, acc1[2 * q]);
            acc0[2 * q + 1] = ffma2(w.y, xk0, acc0[2 * q + 1]);
            acc1[2 * q + 1] = ffma2(w.y, xk1, acc1[2 * q + 1]);
        }
        u64 w12 = sW1[k * J_STRIDE + 12];
        acc0[12] = ffma2(w12, xk0, acc0[12]);
        acc1[12] = ffma2(w12, xk1, acc1[12]);
    }

    float y0[2 * J_PAIRS], y1[2 * J_PAIRS];
    #pragma unroll
    for (int p = 0; p < J_PAIRS; p++) {
        float lo, hi;
        upk2(acc0[p], lo, hi);
        y0[2 * p]     = fmaxf(lo, 0.0f);
        y0[2 * p + 1] = fmaxf(hi, 0.0f);
        upk2(acc1[p], lo, hi);
        y1[2 * p]     = fmaxf(lo, 0.0f);
        y1[2 * p + 1] = fmaxf(hi, 0.0f);
    }

    // ---- Layer 2: weights via constant port (LDC) ----
    u64 z0[I_PAIRS], z1[I_PAIRS];
    #pragma unroll
    for (int p = 0; p < I_PAIRS; p++) { z0[p] = cP.b2[p]; z1[p] = cP.b2[p]; }

    #pragma unroll
    for (int k = 0; k < NUM_IN; k++) {
        u64 yk0 = pk2s(y0[k]);
        u64 yk1 = pk2s(y1[k]);
        const ulonglong2* wv = reinterpret_cast<const ulonglong2*>(cP.w2[k]);
        #pragma unroll
        for (int q = 0; q < 5; q++) {
            ulonglong2 w = wv[q];
            z0[2 * q]     = ffma2(w.x, yk0, z0[2 * q]);
            z1[2 * q]     = ffma2(w.x, yk1, z1[2 * q]);
            z0[2 * q + 1] = ffma2(w.y, yk0, z0[2 * q + 1]);
            z1[2 * q + 1] = ffma2(w.y, yk1, z1[2 * q + 1]);
        }
    }

    if (!active) return;

    float zl[NUM_OUT], zh[NUM_OUT];
    #pragma unroll
    for (int p = 0; p < I_PAIRS; p++) {
        float lo, hi;
        upk2(z0[p], lo, hi);
        zl[2 * p]     = fmaxf(lo, 0.0f);
        zl[2 * p + 1] = fmaxf(hi, 0.0f);
        upk2(z1[p], lo, hi);
        zh[2 * p]     = fmaxf(lo, 0.0f);
        zh[2 * p + 1] = fmaxf(hi, 0.0f);
    }

    // ---- Scatter to the three concatenated output blocks ----
    float4* ov = reinterpret_cast<float4*>(out);
    long Ef4_b1 = 2L * (long)E;
    long Ef4_b2 = 4L * (long)E;

    ov[2 * e0]              = make_float4(zl[0],  zl[1],  zl[2],  zl[3]);
    ov[2 * e0 + 1]          = make_float4(zl[4],  zl[5],  zl[6],  zl[7]);
    ov[Ef4_b1 + 2 * e0]     = make_float4(zl[8],  zl[9],  zl[10], zl[11]);
    ov[Ef4_b1 + 2 * e0 + 1] = make_float4(zl[12], zl[13], zl[14], zl[15]);
    ov[Ef4_b2 + e0]         = make_float4(zl[16], zl[17], zl[18], zl[19]);

    if (have_e1) {
        long e1 = e0 + 1;
        ov[2 * e1]              = make_float4(zh[0],  zh[1],  zh[2],  zh[3]);
        ov[2 * e1 + 1]          = make_float4(zh[4],  zh[5],  zh[6],  zh[7]);
        ov[Ef4_b1 + 2 * e1]     = make_float4(zh[8],  zh[9],  zh[10], zh[11]);
        ov[Ef4_b1 + 2 * e1 + 1] = make_float4(zh[12], zh[13], zh[14], zh[15]);
        ov[Ef4_b2 + e1]         = make_float4(zh[16], zh[17], zh[18], zh[19]);
    }
}

extern "C" void kernel_launch(void* const* d_in, const int* in_sizes, int n_in,
                              void* d_out, int out_size)
{
    const float* r          = (const float*)d_in[0];
    const float* a_data     = (const float*)d_in[1];
    const float* a_material = (const float*)d_in[2];
    const float* a_influx   = (const float*)d_in[3];
    const float* b_data     = (const float*)d_in[4];
    const float* b_material = (const float*)d_in[5];
    const float* b_influx   = (const float*)d_in[6];
    const float* e_data     = (const float*)d_in[7];
    const float* W1         = (const float*)d_in[8];
    const float* b1         = (const float*)d_in[9];
    const float* W2         = (const float*)d_in[10];
    const float* b2         = (const float*)d_in[11];
    float* out = (float*)d_out;

    int E = in_sizes[0];

    // 1) Pack layer-2 weights + biases into __device__ scratch.
    prep_kernel<<<4, 128>>>(b1, W2, b2);

    // 2) D2D copy scratch -> __constant__ symbol (graph-capturable memcpy node).
    void* cp_addr = nullptr;
    void* scr_addr = nullptr;
    cudaGetSymbolAddress(&cp_addr, cP);
    cudaGetSymbolAddress(&scr_addr, dScratch);
    cudaMemcpyAsync(cp_addr, scr_addr, sizeof(CParams), cudaMemcpyDeviceToDevice, 0);

    // 3) Main kernel: 2 edges per thread; W1 staged to shared per block.
    long pairs = ((long)E + 1) / 2;
    int threads = 128;
    int blocks = (int)((pairs + threads - 1) / threads);
    edge_mlp_kernel<<<blocks, threads>>>(r, a_data, a_material, a_influx,
                                         b_data, b_material, b_influx, e_data,
                                         W1, out, E);
}